// round 16
// baseline (speedup 1.0000x reference)
#include <cuda_runtime.h>
#include <cuda_fp16.h>
#include <cstdint>

#define N_ROWS 8192
#define D_DIM  512
#define BM 128
#define BN 128
#define BK 64                   // f16 elems per k-step (4 k16 substeps)
#define NKS (D_DIM / BK)        // 8 k-steps per tile
#define NB  (N_ROWS / BM)       // 64
#define NTILES (NB * (NB + 1) / 2)   // 2080
#define PITCH 144               // 9 x 16B groups: (r+c) mod 8 distinct, additive
#define STAGES 3
#define STAGE_BYTES (256 * PITCH)            // 36864: A(128)+B(128) rows
#define SMEM_BYTES (STAGES * STAGE_BYTES)    // 110592 B

#define EXP10 22026.465794806718f
#define SCALE 14.426950408889634f   // (1/0.1)*log2(e), folded into g_fb

// ---- scratch ----
__device__ __half g_fa[N_ROWS * D_DIM];
__device__ __half g_fb[N_ROWS * D_DIM];
__device__ float g_pos[N_ROWS];
__device__ float g_tot[N_ROWS];
__device__ int   g_cl[N_ROWS];

// =============================== helpers ===================================
__device__ __forceinline__ uint32_t smem_u32(const void* p) {
    return (uint32_t)__cvta_generic_to_shared(p);
}
__device__ __forceinline__ void cp16(uint32_t saddr, const void* g) {
    asm volatile("cp.async.cg.shared.global [%0], [%1], 16;" :: "r"(saddr), "l"(g));
}
__device__ __forceinline__ void ldsm_x4(uint32_t addr, uint32_t* r) {
    asm volatile("ldmatrix.sync.aligned.m8n8.x4.shared.b16 {%0,%1,%2,%3},[%4];"
                 : "=r"(r[0]), "=r"(r[1]), "=r"(r[2]), "=r"(r[3]) : "r"(addr));
}
// fp16-accumulate HMMA: C{2xh2} += A{4} * B{2}
__device__ __forceinline__ void mma16816h(uint32_t* c, const uint32_t* a,
                                          uint32_t b0, uint32_t b1) {
    asm volatile(
        "mma.sync.aligned.m16n8k16.row.col.f16.f16.f16.f16 "
        "{%0,%1},{%2,%3,%4,%5},{%6,%7},{%0,%1};"
        : "+r"(c[0]), "+r"(c[1])
        : "r"(a[0]), "r"(a[1]), "r"(a[2]), "r"(a[3]), "r"(b0), "r"(b1));
}
__device__ __forceinline__ float ex2(float x) {
    float e;
    asm("ex2.approx.f32 %0, %1;" : "=f"(e) : "f"(x));
    return e;
}

// =============================== small kernels ==============================
__global__ void init_kernel(const int* ca, float* out) {
    int i = blockIdx.x * blockDim.x + threadIdx.x;
    if (i == 0) out[0] = 0.0f;
    if (i >= N_ROWS) return;
    bool is64 = (ca[1] == 0) && (ca[3] == 0) && (ca[5] == 0) && (ca[7] == 0);
    g_cl[i]  = is64 ? ca[2 * i] : ca[i];
    g_pos[i] = 0.0f;
    g_tot[i] = 0.0f;
}

__global__ void norm_kernel(const float* __restrict__ f) {
    int row = blockIdx.x;
    const float* fr = f + (size_t)row * D_DIM;
    float v[4];
    float ss = 0.0f;
#pragma unroll
    for (int k = 0; k < 4; k++) { v[k] = fr[threadIdx.x + 128 * k]; ss += v[k] * v[k]; }
#pragma unroll
    for (int o = 16; o; o >>= 1) ss += __shfl_xor_sync(0xFFFFFFFFu, ss, o);
    __shared__ float s[4];
    if ((threadIdx.x & 31) == 0) s[threadIdx.x >> 5] = ss;
    __syncthreads();
    ss = s[0] + s[1] + s[2] + s[3];
    float r = 1.0f / fmaxf(sqrtf(ss), 1e-12f);
#pragma unroll
    for (int k = 0; k < 4; k++) {
        float x = v[k] * r;
        size_t idx = (size_t)row * D_DIM + threadIdx.x + 128 * k;
        g_fa[idx] = __float2half(x);
        g_fb[idx] = __float2half(x * SCALE);
    }
}

__global__ void dummy_kernel() {}   // ncu capture alignment (-s 5 lands on gemm)

__global__ void loss_kernel(float* __restrict__ out) {
    int i = blockIdx.x * blockDim.x + threadIdx.x;
    float sum = logf((g_tot[i] + 1e-8f) / g_pos[i]);
#pragma unroll
    for (int o = 16; o; o >>= 1) sum += __shfl_xor_sync(0xFFFFFFFFu, sum, o);
    __shared__ float s[8];
    if ((threadIdx.x & 31) == 0) s[threadIdx.x >> 5] = sum;
    __syncthreads();
    if (threadIdx.x < 32) {
        float v = (threadIdx.x < 8) ? s[threadIdx.x] : 0.0f;
#pragma unroll
        for (int o = 4; o; o >>= 1) v += __shfl_xor_sync(0xFFFFFFFFu, v, o);
        if (threadIdx.x == 0) atomicAdd(out, v);
    }
}

// =============================== main GEMM ==================================
// One 128x128 upper-triangular tile per CTA (2080 CTAs).
// 128 threads = 4 warps (2M x 2N), warp tile 64x64, fp16 HMMA (fp16 acc).
// BK=64, PITCH=144 additive conflict-free, 3 stages, ONE barrier per k-step
// (8 per tile). 0.25 ldsm.x4/MMA; 32-MMA independent runs per B fragment.
__global__ void __launch_bounds__(128, 2) gemm_hmma() {
    extern __shared__ char sm[];

    const int tid  = threadIdx.x;
    const int lane = tid & 31;
    const int w    = tid >> 5;
    const int wm   = w & 1;
    const int wn   = w >> 1;

    // ---- triangular tile map: t -> (bi, bj), bi <= bj ----
    const int t = blockIdx.x;
    int bi = (int)((129.0f - sqrtf(16641.0f - 8.0f * (float)t)) * 0.5f);
    while ((bi + 1) * NB - ((bi + 1) * bi) / 2 <= t) bi++;
    while (bi * NB - (bi * (bi - 1)) / 2 > t) bi--;
    const int bj = bi + (t - (bi * NB - (bi * (bi - 1)) / 2));
    const int i0 = bi * BM;
    const int j0 = bj * BN;
    const bool isdiag = (bi == bj);

    const uint32_t sm_base = smem_u32(sm);

    // ---- staging: lane -> chunk (l&7), rows (tid>>3)+16q (128 threads) ----
    const int c  = lane & 7;
    const int r0 = tid >> 3;            // 0..15
    const uint32_t sw0 = (uint32_t)(r0 * PITCH + c * 16);
    const __half* gA = g_fa + (size_t)(i0 + r0) * D_DIM + c * 8;
    const __half* gB = g_fb + (size_t)(j0 + r0) * D_DIM + c * 8;

    auto prefetch = [&](int g) {
        const uint32_t st = sm_base + (uint32_t)(g % STAGES) * STAGE_BYTES + sw0;
        const __half* ga = gA + g * BK;
        const __half* gb = gB + g * BK;
#pragma unroll
        for (int q = 0; q < 8; q++) {
            cp16(st + q * (16 * PITCH), ga + q * 16 * D_DIM);
            cp16(st + 128 * PITCH + q * (16 * PITCH), gb + q * 16 * D_DIM);
        }
        asm volatile("cp.async.commit_group;" ::: "memory");
    };

    // ---- ldsm base addresses (all further offsets immediates) ----
    const int a_row = wm * 64 + (lane & 15);
    const uint32_t a_base = sm_base + (uint32_t)(a_row * PITCH) +
                            (uint32_t)((lane >> 4) << 4);
    const int b_row = wn * 64 + (lane & 7) + ((lane >> 4) << 3);
    const uint32_t b_base = sm_base + (uint32_t)(128 * PITCH) +
                            (uint32_t)(b_row * PITCH) +
                            (uint32_t)(((lane >> 3) & 1) << 4);

    uint32_t acc[4][8][2];              // fp16 half2 fragments, 64 regs
#pragma unroll
    for (int mi = 0; mi < 4; mi++)
#pragma unroll
        for (int nf = 0; nf < 8; nf++) {
            acc[mi][nf][0] = 0u;
            acc[mi][nf][1] = 0u;
        }

    prefetch(0);
    prefetch(1);

    for (int g = 0; g < NKS; g++) {
        asm volatile("cp.async.wait_group 1;" ::: "memory");
        __syncthreads();
        if (g + 2 < NKS) prefetch(g + 2);
        else asm volatile("cp.async.commit_group;" ::: "memory");

        const uint32_t so = (uint32_t)(g % STAGES) * STAGE_BYTES;
        const uint32_t sa = a_base + so;
        const uint32_t sb = b_base + so;

#pragma unroll
        for (int s = 0; s < 4; s++) {            // k16 substeps within BK=64
            uint32_t a[4][4];
#pragma unroll
            for (int mi = 0; mi < 4; mi++)
                ldsm_x4(sa + (uint32_t)(mi * 16 * PITCH + s * 32), a[mi]);
#pragma unroll
            for (int np = 0; np < 4; np++) {
                uint32_t b[4];
                ldsm_x4(sb + (uint32_t)(np * 16 * PITCH + s * 32), b);
#pragma unroll
                for (int mi = 0; mi < 4; mi++) {
                    mma16816h(acc[mi][np * 2],     a[mi], b[0], b[1]);
                    mma16816h(acc[mi][np * 2 + 1], a[mi], b[2], b[3]);
                }
            }
        }
    }

    // ---- epilogue: rows -> block bi, cols -> block bj (symmetric reuse) ----
    const int rbase = wm * 64 + (lane >> 2);
    int ci[8];
#pragma unroll
    for (int r = 0; r < 8; r++)
        ci[r] = g_cl[i0 + rbase + (r >> 1) * 16 + (r & 1) * 8];

    float tr[8], pr[8];
#pragma unroll
    for (int r = 0; r < 8; r++) { tr[r] = 0.0f; pr[r] = 0.0f; }

#pragma unroll
    for (int nf = 0; nf < 8; nf++) {
        const int colb = wn * 64 + nf * 8 + (lane & 3) * 2;
        const int2 cjp = *(const int2*)&g_cl[j0 + colb];
        float ct[2] = {0, 0}, cp[2] = {0, 0};
#pragma unroll
        for (int mi = 0; mi < 4; mi++) {
#pragma unroll
            for (int h = 0; h < 2; h++) {
                const float2 ef = __half22float2(
                    *reinterpret_cast<const __half2*>(&acc[mi][nf][h]));
#pragma unroll
                for (int vb = 0; vb < 2; vb++) {
                    const int ridx = mi * 2 + h;
                    float e = ex2(vb ? ef.y : ef.x);
                    if (isdiag && (rbase + mi * 16 + h * 8 == colb + vb)) e = EXP10;
                    const bool m = (ci[ridx] == (vb ? cjp.y : cjp.x));
                    tr[ridx] += e;
                    if (m) pr[ridx] += e;
                    ct[vb] += e;
                    if (m) cp[vb] += e;
                }
            }
        }
        if (!isdiag) {
#pragma unroll
            for (int o = 4; o <= 16; o <<= 1) {
#pragma unroll
                for (int vb = 0; vb < 2; vb++) {
                    ct[vb] += __shfl_xor_sync(0xFFFFFFFFu, ct[vb], o);
                    cp[vb] += __shfl_xor_sync(0xFFFFFFFFu, cp[vb], o);
                }
            }
            if (lane < 4) {
                atomicAdd(&g_tot[j0 + colb + 0], ct[0]);
                atomicAdd(&g_tot[j0 + colb + 1], ct[1]);
                atomicAdd(&g_pos[j0 + colb + 0], cp[0]);
                atomicAdd(&g_pos[j0 + colb + 1], cp[1]);
            }
        }
    }

#pragma unroll
    for (int r = 0; r < 8; r++) {
#pragma unroll
        for (int o = 1; o <= 2; o <<= 1) {
            tr[r] += __shfl_xor_sync(0xFFFFFFFFu, tr[r], o);
            pr[r] += __shfl_xor_sync(0xFFFFFFFFu, pr[r], o);
        }
    }
    if ((lane & 3) == 0) {
#pragma unroll
        for (int r = 0; r < 8; r++) {
            const int row = i0 + rbase + (r >> 1) * 16 + (r & 1) * 8;
            atomicAdd(&g_tot[row], tr[r]);
            atomicAdd(&g_pos[row], pr[r]);
        }
    }
}

// =============================== launch =====================================
extern "C" void kernel_launch(void* const* d_in, const int* in_sizes, int n_in,
                              void* d_out, int out_size) {
    const float* feat = (const float*)d_in[0];
    const int*   ca   = (const int*)d_in[1];

    static bool attr_done = false;
    if (!attr_done) {
        cudaFuncSetAttribute(gemm_hmma, cudaFuncAttributeMaxDynamicSharedMemorySize,
                             SMEM_BYTES);
        attr_done = true;
    }

    init_kernel<<<(N_ROWS + 255) / 256, 256>>>(ca, (float*)d_out);
    norm_kernel<<<N_ROWS, 128>>>(feat);
    dummy_kernel<<<1, 32>>>();
    gemm_hmma<<<NTILES, 128, SMEM_BYTES>>>();
    loss_kernel<<<N_ROWS / 256, 256>>>((float*)d_out);
}

// round 17
// speedup vs baseline: 1.1554x; 1.1554x over previous
#include <cuda_runtime.h>
#include <cuda_fp16.h>
#include <cstdint>

#define N_ROWS 8192
#define D_DIM  512
#define BM 128
#define BN 128
#define BK 64                   // f16 elems per k-step (4 k16 substeps)
#define NKS (D_DIM / BK)        // 8 k-steps per tile
#define NB  (N_ROWS / BM)       // 64
#define NTILES (NB * (NB + 1) / 2)   // 2080
#define PITCH 144               // 9 x 16B groups: (r+c) mod 8 distinct, additive
#define STAGES 3
#define STAGE_BYTES (256 * PITCH)            // 36864: A(128)+B(128) rows
#define SMEM_BYTES (STAGES * STAGE_BYTES)    // 110592 B

#define EXP10 22026.465794806718f
#define SCALE 14.426950408889634f   // (1/0.1)*log2(e), folded into g_fb

// ---- scratch ----
__device__ __half g_fa[N_ROWS * D_DIM];
__device__ __half g_fb[N_ROWS * D_DIM];
__device__ float g_pos[N_ROWS];
__device__ float g_tot[N_ROWS];
__device__ int   g_cl[N_ROWS];

// =============================== helpers ===================================
__device__ __forceinline__ uint32_t smem_u32(const void* p) {
    return (uint32_t)__cvta_generic_to_shared(p);
}
__device__ __forceinline__ void cp16(uint32_t saddr, const void* g) {
    asm volatile("cp.async.cg.shared.global [%0], [%1], 16;" :: "r"(saddr), "l"(g));
}
__device__ __forceinline__ void ldsm_x4(uint32_t addr, uint32_t* r) {
    asm volatile("ldmatrix.sync.aligned.m8n8.x4.shared.b16 {%0,%1,%2,%3},[%4];"
                 : "=r"(r[0]), "=r"(r[1]), "=r"(r[2]), "=r"(r[3]) : "r"(addr));
}
// fp16-accumulate HMMA: C{2xh2} += A{4} * B{2}
__device__ __forceinline__ void mma16816h(uint32_t* c, const uint32_t* a,
                                          uint32_t b0, uint32_t b1) {
    asm volatile(
        "mma.sync.aligned.m16n8k16.row.col.f16.f16.f16.f16 "
        "{%0,%1},{%2,%3,%4,%5},{%6,%7},{%0,%1};"
        : "+r"(c[0]), "+r"(c[1])
        : "r"(a[0]), "r"(a[1]), "r"(a[2]), "r"(a[3]), "r"(b0), "r"(b1));
}
__device__ __forceinline__ float ex2(float x) {
    float e;
    asm("ex2.approx.f32 %0, %1;" : "=f"(e) : "f"(x));
    return e;
}

// =============================== norm + init (fused) ========================
// One block (128 threads) per row: L2-normalize, quantize to f16 (plain and
// pre-scaled), convert this row's cluster id, zero accumulators.
__global__ void norm_kernel(const float* __restrict__ f,
                            const int* __restrict__ ca,
                            float* __restrict__ out) {
    const int row = blockIdx.x;
    const float4 v = ((const float4*)(f + (size_t)row * D_DIM))[threadIdx.x];
    float ss = v.x * v.x + v.y * v.y + v.z * v.z + v.w * v.w;
#pragma unroll
    for (int o = 16; o; o >>= 1) ss += __shfl_xor_sync(0xFFFFFFFFu, ss, o);
    __shared__ float s[4];
    if ((threadIdx.x & 31) == 0) s[threadIdx.x >> 5] = ss;
    __syncthreads();
    ss = s[0] + s[1] + s[2] + s[3];
    const float r = 1.0f / fmaxf(sqrtf(ss), 1e-12f);

    __half2* fa = (__half2*)(g_fa + (size_t)row * D_DIM) + threadIdx.x * 2;
    __half2* fb = (__half2*)(g_fb + (size_t)row * D_DIM) + threadIdx.x * 2;
    fa[0] = __floats2half2_rn(v.x * r, v.y * r);
    fa[1] = __floats2half2_rn(v.z * r, v.w * r);
    fb[0] = __floats2half2_rn(v.x * r * SCALE, v.y * r * SCALE);
    fb[1] = __floats2half2_rn(v.z * r * SCALE, v.w * r * SCALE);

    if (threadIdx.x == 0) {
        // int64 detection: high words of little-endian int64 are zero (ids 0..63)
        const bool is64 = (ca[1] == 0) && (ca[3] == 0) && (ca[5] == 0) && (ca[7] == 0);
        g_cl[row]  = is64 ? ca[2 * row] : ca[row];
        g_pos[row] = 0.0f;
        g_tot[row] = 0.0f;
        if (row == 0) out[0] = 0.0f;
    }
}

__global__ void loss_kernel(float* __restrict__ out) {
    int i = blockIdx.x * blockDim.x + threadIdx.x;
    float sum = logf((g_tot[i] + 1e-8f) / g_pos[i]);
#pragma unroll
    for (int o = 16; o; o >>= 1) sum += __shfl_xor_sync(0xFFFFFFFFu, sum, o);
    __shared__ float s[4];
    if ((threadIdx.x & 31) == 0) s[threadIdx.x >> 5] = sum;
    __syncthreads();
    if (threadIdx.x < 32) {
        float v = (threadIdx.x < 4) ? s[threadIdx.x] : 0.0f;
#pragma unroll
        for (int o = 2; o; o >>= 1) v += __shfl_xor_sync(0xFFFFFFFFu, v, o);
        if (threadIdx.x == 0) atomicAdd(out, v);
    }
}

// =============================== main GEMM ==================================
// One 128x128 upper-triangular tile per CTA (2080 CTAs).
// 256 threads = 8 warps (4M x 2N), warp tile 32x64, fp16 in / fp16 acc HMMA.
// BK=64, PITCH=144 additive conflict-free layout, 3 stages, 8 barriers/tile.
// (R14 mainloop, validated at 98.8us / tensor 58.9%.)
__global__ void __launch_bounds__(256, 2) gemm_hmma() {
    extern __shared__ char sm[];

    const int tid  = threadIdx.x;
    const int lane = tid & 31;
    const int w    = tid >> 5;
    const int wm   = w & 3;
    const int wn   = w >> 2;

    // ---- triangular tile map: t -> (bi, bj), bi <= bj ----
    const int t = blockIdx.x;
    int bi = (int)((129.0f - sqrtf(16641.0f - 8.0f * (float)t)) * 0.5f);
    while ((bi + 1) * NB - ((bi + 1) * bi) / 2 <= t) bi++;
    while (bi * NB - (bi * (bi - 1)) / 2 > t) bi--;
    const int bj = bi + (t - (bi * NB - (bi * (bi - 1)) / 2));
    const int i0 = bi * BM;
    const int j0 = bj * BN;
    const bool isdiag = (bi == bj);

    const uint32_t sm_base = smem_u32(sm);

    // ---- staging: lane -> chunk (l&7), row tid>>3 (+32q) ----
    const int c  = lane & 7;
    const int r0 = tid >> 3;            // 0..31
    const uint32_t sw0 = (uint32_t)(r0 * PITCH + c * 16);
    const __half* gA = g_fa + (size_t)(i0 + r0) * D_DIM + c * 8;
    const __half* gB = g_fb + (size_t)(j0 + r0) * D_DIM + c * 8;

    auto prefetch = [&](int g) {
        const uint32_t st = sm_base + (uint32_t)(g % STAGES) * STAGE_BYTES + sw0;
        const __half* ga = gA + g * BK;
        const __half* gb = gB + g * BK;
#pragma unroll
        for (int q = 0; q < 4; q++) {
            cp16(st + q * (32 * PITCH), ga + q * 32 * D_DIM);
            cp16(st + 128 * PITCH + q * (32 * PITCH), gb + q * 32 * D_DIM);
        }
        asm volatile("cp.async.commit_group;" ::: "memory");
    };

    // ---- ldsm base addresses (all further offsets immediates) ----
    const int a_row = wm * 32 + (lane & 15);
    const uint32_t a_base = sm_base + (uint32_t)(a_row * PITCH) +
                            (uint32_t)((lane >> 4) << 4);
    const int b_row = wn * 64 + (lane & 7) + ((lane >> 4) << 3);
    const uint32_t b_base = sm_base + (uint32_t)(128 * PITCH) +
                            (uint32_t)(b_row * PITCH) +
                            (uint32_t)(((lane >> 3) & 1) << 4);

    uint32_t acc[2][8][2];              // fp16 half2 accumulator fragments
#pragma unroll
    for (int mi = 0; mi < 2; mi++)
#pragma unroll
        for (int nf = 0; nf < 8; nf++) {
            acc[mi][nf][0] = 0u;
            acc[mi][nf][1] = 0u;
        }

    prefetch(0);
    prefetch(1);

    for (int g = 0; g < NKS; g++) {
        asm volatile("cp.async.wait_group 1;" ::: "memory");
        __syncthreads();
        if (g + 2 < NKS) prefetch(g + 2);
        else asm volatile("cp.async.commit_group;" ::: "memory");

        const uint32_t so = (uint32_t)(g % STAGES) * STAGE_BYTES;
        const uint32_t sa = a_base + so;
        const uint32_t sb = b_base + so;

#pragma unroll
        for (int s = 0; s < 4; s++) {            // k16 substeps within BK=64
            uint32_t a[2][4];
#pragma unroll
            for (int mi = 0; mi < 2; mi++)
                ldsm_x4(sa + (uint32_t)(mi * 16 * PITCH + s * 32), a[mi]);
#pragma unroll
            for (int np = 0; np < 4; np++) {
                uint32_t b[4];
                ldsm_x4(sb + (uint32_t)(np * 16 * PITCH + s * 32), b);
#pragma unroll
                for (int mi = 0; mi < 2; mi++) {
                    mma16816h(acc[mi][np * 2],     a[mi], b[0], b[1]);
                    mma16816h(acc[mi][np * 2 + 1], a[mi], b[2], b[3]);
                }
            }
        }
    }

    // ---- epilogue: rows -> block bi, cols -> block bj (symmetric reuse) ----
    const int rbase = wm * 32 + (lane >> 2);
    int ci[4];
#pragma unroll
    for (int r = 0; r < 4; r++)
        ci[r] = g_cl[i0 + rbase + (r >> 1) * 16 + (r & 1) * 8];

    float tr[4] = {0, 0, 0, 0}, pr[4] = {0, 0, 0, 0};

#pragma unroll
    for (int nf = 0; nf < 8; nf++) {
        const int colb = wn * 64 + nf * 8 + (lane & 3) * 2;
        const int2 cjp = *(const int2*)&g_cl[j0 + colb];
        float ct[2] = {0, 0}, cp[2] = {0, 0};
#pragma unroll
        for (int mi = 0; mi < 2; mi++) {
#pragma unroll
            for (int h = 0; h < 2; h++) {
                const float2 ef = __half22float2(
                    *reinterpret_cast<const __half2*>(&acc[mi][nf][h]));
#pragma unroll
                for (int vb = 0; vb < 2; vb++) {
                    const int ridx = mi * 2 + h;
                    float e = ex2(vb ? ef.y : ef.x);
                    if (isdiag && (rbase + mi * 16 + h * 8 == colb + vb)) e = EXP10;
                    const bool m = (ci[ridx] == (vb ? cjp.y : cjp.x));
                    tr[ridx] += e;
                    if (m) pr[ridx] += e;
                    ct[vb] += e;
                    if (m) cp[vb] += e;
                }
            }
        }
        if (!isdiag) {
#pragma unroll
            for (int o = 4; o <= 16; o <<= 1) {
#pragma unroll
                for (int vb = 0; vb < 2; vb++) {
                    ct[vb] += __shfl_xor_sync(0xFFFFFFFFu, ct[vb], o);
                    cp[vb] += __shfl_xor_sync(0xFFFFFFFFu, cp[vb], o);
                }
            }
            if (lane < 4) {
                atomicAdd(&g_tot[j0 + colb + 0], ct[0]);
                atomicAdd(&g_tot[j0 + colb + 1], ct[1]);
                atomicAdd(&g_pos[j0 + colb + 0], cp[0]);
                atomicAdd(&g_pos[j0 + colb + 1], cp[1]);
            }
        }
    }

#pragma unroll
    for (int r = 0; r < 4; r++) {
#pragma unroll
        for (int o = 1; o <= 2; o <<= 1) {
            tr[r] += __shfl_xor_sync(0xFFFFFFFFu, tr[r], o);
            pr[r] += __shfl_xor_sync(0xFFFFFFFFu, pr[r], o);
        }
    }
    if ((lane & 3) == 0) {
#pragma unroll
        for (int r = 0; r < 4; r++) {
            const int row = i0 + rbase + (r >> 1) * 16 + (r & 1) * 8;
            atomicAdd(&g_tot[row], tr[r]);
            atomicAdd(&g_pos[row], pr[r]);
        }
    }
}

// =============================== launch =====================================
extern "C" void kernel_launch(void* const* d_in, const int* in_sizes, int n_in,
                              void* d_out, int out_size) {
    const float* feat = (const float*)d_in[0];
    const int*   ca   = (const int*)d_in[1];

    static bool attr_done = false;
    if (!attr_done) {
        cudaFuncSetAttribute(gemm_hmma, cudaFuncAttributeMaxDynamicSharedMemorySize,
                             SMEM_BYTES);
        attr_done = true;
    }

    norm_kernel<<<N_ROWS, 128>>>(feat, ca, (float*)d_out);
    gemm_hmma<<<NTILES, 256, SMEM_BYTES>>>();
    loss_kernel<<<N_ROWS / 128, 128>>>((float*)d_out);
}